// round 6
// baseline (speedup 1.0000x reference)
#include <cuda_runtime.h>

#define TT 300

// ---------------- static scratch (no allocations allowed) ----------------
__device__ float g_a [78643200];   // conv/pool outputs (max: layer1, 16*16*32*32*300)
__device__ float g_sA[78643200];   // spike ping buffer
__device__ float g_sB[19660800];   // spike pong buffer
__device__ float g_u [48000];      // dense pre-psp output

// ---------------- IIR constants (exact double) ----------------
// eps[k] = (k/10)*e*d^k, d = exp(-0.1). Truncation at k<=99 via delayed tail IIR.
#define DD  0.9048374180359595     // exp(-0.1)
#define CC1 0.2718281828459045     // e/10
#define CC2 1.2340980408667956e-3  // 10*exp(-9)
#define CC3 1.2340980408667956e-5  // 0.1*exp(-9)

// =====================================================================
// Spatial conv: out[b,co,oh,ow,t] = sum_{ci,kh,kw} W[co,ci,kh,kw]*in[b,ci,ih,iw,t]
// threads = t (coalesced). Per-ci fp32 partial chain (<=25 terms, ~1e-6 error),
// partials combined in DOUBLE -> conv output within ~1e-6 of the true value,
// well inside the reference's own fp32 rounding (~2e-5).
// =====================================================================
template<int CI,int CO_T,int CO_FULL,int KH,int KW,int HIN,int WIN,int HOUT,int WOUT,int PAD>
__global__ void __launch_bounds__(320)
conv_kernel(const float* __restrict__ in, const float* __restrict__ w,
            float* __restrict__ out, int co_base)
{
    __shared__ __align__(16) float sw[CI*KH*KW*CO_T];
    const int tid = threadIdx.x;
    const int ow = blockIdx.x, oh = blockIdx.y, b = blockIdx.z;

    for (int i = tid; i < CI*KH*KW*CO_T; i += 320) {
        int k = i / CO_T, co = i % CO_T;
        sw[i] = w[(co_base + co)*(CI*KH*KW) + k];
    }
    __syncthreads();

    const int t = tid;
    if (t >= TT) return;

    double accd[CO_T];
#pragma unroll
    for (int c = 0; c < CO_T; c++) accd[c] = 0.0;

    for (int ci = 0; ci < CI; ci++) {
        float pacc[CO_T];
#pragma unroll
        for (int c = 0; c < CO_T; c++) pacc[c] = 0.f;

#pragma unroll
        for (int kh = 0; kh < KH; kh++) {
            const int ih = oh + kh - PAD;
#pragma unroll
            for (int kw = 0; kw < KW; kw++) {
                const int iw = ow + kw - PAD;
                const bool valid = ((unsigned)ih < (unsigned)HIN) && ((unsigned)iw < (unsigned)WIN);
                const float* p = in + ((((b*CI + ci)*HIN + ih)*WIN) + iw)*TT;
                const float x = valid ? p[t] : 0.f;
                const float4* wv = reinterpret_cast<const float4*>(&sw[((ci*KH + kh)*KW + kw)*CO_T]);
#pragma unroll
                for (int c4 = 0; c4 < CO_T/4; c4++) {
                    float4 wq = wv[c4];
                    pacc[c4*4+0] = fmaf(wq.x, x, pacc[c4*4+0]);
                    pacc[c4*4+1] = fmaf(wq.y, x, pacc[c4*4+1]);
                    pacc[c4*4+2] = fmaf(wq.z, x, pacc[c4*4+2]);
                    pacc[c4*4+3] = fmaf(wq.w, x, pacc[c4*4+3]);
                }
            }
        }
#pragma unroll
        for (int c = 0; c < CO_T; c++) accd[c] += (double)pacc[c];
    }

#pragma unroll
    for (int c = 0; c < CO_T; c++) {
        float* q = out + ((((b*CO_FULL) + (co_base + c))*HOUT + oh)*WOUT + ow)*TT;
        q[t] = (float)accd[c];
    }
}

// =====================================================================
// SLAYER 2x2 sum-pool, weight 1.1*theta = 11 (exact in fp32 for 0/1 spikes)
// =====================================================================
template<int C,int HIN,int WIN>
__global__ void pool_kernel(const float* __restrict__ in, float* __restrict__ out)
{
    const int HO = HIN/2, WO = WIN/2;
    const int t = blockIdx.x*128 + threadIdx.x;
    if (t >= TT) return;
    const int z  = blockIdx.z;
    const int ho = z % HO;
    const int c  = (z / HO) % C;
    const int b  = z / (HO*C);
    const int wo = blockIdx.y;
    const float* p = in + (((b*C + c)*HIN + 2*ho)*WIN + 2*wo)*TT + t;
    float v = p[0] + p[TT] + p[WIN*TT] + p[(WIN+1)*TT];
    out[(((b*C + c)*HO + ho)*WO + wo)*TT + t] = 11.0f * v;
}

// =====================================================================
// PSP: exact truncated alpha-kernel conv via double IIR + delayed-tail IIR
// (error ~1e-14 vs true truncated-FIR value), fused with the bit-exact
// refractory threshold scan. 128 neurons/block; 32-t smem tiles for coalescing.
// =====================================================================
__global__ void __launch_bounds__(128)
psp_spike_kernel(const float* __restrict__ a, float* __restrict__ s, int N)
{
    __shared__ float sa[128][33];
    __shared__ float sd[128][33];
    const int tid  = threadIdx.x;
    const int lane = tid & 31, wid = tid >> 5;
    const int n0 = blockIdx.x * 128;
    const int n  = n0 + tid;

    double P = 0.0, Z = 0.0, P2 = 0.0, Z2 = 0.0;
    float  r = 0.0f;

    for (int t0 = 0; t0 < TT; t0 += 32) {
        // cooperative coalesced load of current + 100-delayed input tiles
        for (int i = 0; i < 32; i++) {
            const int row = wid*32 + i;
            const int nn  = n0 + row;
            const int t   = t0 + lane;
            float va = 0.f, vd = 0.f;
            if (nn < N) {
                if (t < TT) va = a[nn*TT + t];
                const int td = t - 100;
                if (td >= 0 && td < TT) vd = a[nn*TT + td];
            }
            sa[row][lane] = va;
            sd[row][lane] = vd;
        }
        __syncthreads();

        if (n < N) {
            const int tmax = min(32, TT - t0);
            for (int tt = 0; tt < tmax; tt++) {
                const double x  = (double)sa[tid][tt];
                const double xd = (double)sd[tid][tt];
                Z  = DD * (Z  + P );  P  = DD * P  + x;
                Z2 = DD * (Z2 + P2);  P2 = DD * P2 + xd;
                const double y = CC1*Z - (CC2*P2 + CC3*Z2);
                const float  u = (float)y + r;
                const float sp = (u >= 10.0f) ? 1.0f : 0.0f;
                r = 0.36787944117144233f * (r - 20.0f * sp);   // exact reference recursion
                sa[tid][tt] = sp;
            }
        }
        __syncthreads();

        // coalesced spike write-out
        for (int i = 0; i < 32; i++) {
            const int row = wid*32 + i;
            const int nn  = n0 + row;
            const int t   = t0 + lane;
            if (nn < N && t < TT) s[nn*TT + t] = sa[row][lane];
        }
        __syncthreads();
    }
}

// =====================================================================
// Dense readout: u[b,o,t] = sum_{chw} s5[b,chw,t] * Wf[o,chw]   (chw = 4096)
// DOUBLE accumulation: products exact in double -> result exact to ~1e-13.
// =====================================================================
__global__ void __launch_bounds__(160)
dense_kernel(const float* __restrict__ s5, const float* __restrict__ wf,
             float* __restrict__ u)
{
    __shared__ float wrow[4096];
    const int b = blockIdx.x, o = blockIdx.y;
    const int tid = threadIdx.x;
    for (int i = tid; i < 4096; i += 160) wrow[i] = wf[o*4096 + i];
    __syncthreads();

    const int t0 = tid, t1 = tid + 160;
    const bool v1 = (t1 < TT);
    double a0 = 0.0, a1 = 0.0;
    const float* p = s5 + (size_t)b * 4096 * TT;
    for (int i = 0; i < 4096; i++) {
        const double wv = (double)wrow[i];
        const float x0 = p[i*TT + t0];
        const float x1 = v1 ? p[i*TT + t1] : 0.f;
        a0 += wv * (double)x0;
        a1 += wv * (double)x1;
    }
    float* q = u + (b*10 + o)*TT;
    q[t0] = (float)a0;
    if (v1) q[t1] = (float)a1;
}

// =====================================================================
extern "C" void kernel_launch(void* const* d_in, const int* in_sizes, int n_in,
                              void* d_out, int out_size)
{
    const float *s_in = nullptr, *W1 = nullptr, *W2 = nullptr, *W3 = nullptr, *Wf = nullptr;
    for (int i = 0; i < n_in; i++) {
        switch (in_sizes[i]) {
            case 11097600: s_in = (const float*)d_in[i]; break;   // [16,2,34,34,300]
            case 800:      W1   = (const float*)d_in[i]; break;   // [16,2,5,5]
            case 4608:     W2   = (const float*)d_in[i]; break;   // [32,16,3,3]
            case 18432:    W3   = (const float*)d_in[i]; break;   // [64,32,3,3]
            case 40960:    Wf   = (const float*)d_in[i]; break;   // [10,64,8,8]
        }
    }

    float *a, *sA, *sB, *u;
    cudaGetSymbolAddress((void**)&a,  g_a);
    cudaGetSymbolAddress((void**)&sA, g_sA);
    cudaGetSymbolAddress((void**)&sB, g_sB);
    cudaGetSymbolAddress((void**)&u,  g_u);

    // L1: conv 5x5 pad1  [16,2,34,34] -> [16,16,32,32]
    conv_kernel<2,16,16,5,5,34,34,32,32,1><<<dim3(32,32,16),320>>>(s_in, W1, a, 0);
    psp_spike_kernel<<<2048,128>>>(a, sA, 262144);                 // s1

    // pool 2x2 -> [16,16,16,16]
    pool_kernel<16,32,32><<<dim3(3,16,16*16*16),128>>>(sA, a);
    psp_spike_kernel<<<512,128>>>(a, sB, 65536);                   // s2

    // L3: conv 3x3 pad1 [16,16,16,16] -> [16,32,16,16]
    conv_kernel<16,32,32,3,3,16,16,16,16,1><<<dim3(16,16,16),320>>>(sB, W2, a, 0);
    psp_spike_kernel<<<1024,128>>>(a, sA, 131072);                 // s3

    // pool -> [16,32,8,8]
    pool_kernel<32,16,16><<<dim3(3,8,16*32*8),128>>>(sA, a);
    psp_spike_kernel<<<256,128>>>(a, sB, 32768);                   // s4

    // L5: conv 3x3 pad1 [16,32,8,8] -> [16,64,8,8]  (two CO halves, reg-sized)
    conv_kernel<32,32,64,3,3,8,8,8,8,1><<<dim3(8,8,16),320>>>(sB, W3, a, 0);
    conv_kernel<32,32,64,3,3,8,8,8,8,1><<<dim3(8,8,16),320>>>(sB, W3, a, 32);
    psp_spike_kernel<<<512,128>>>(a, sA, 65536);                   // s5

    // dense readout + final psp/spike straight into d_out
    dense_kernel<<<dim3(16,10),160>>>(sA, Wf, u);
    psp_spike_kernel<<<2,128>>>(u, (float*)d_out, 160);
}

// round 8
// speedup vs baseline: 3.2561x; 3.2561x over previous
#include <cuda_runtime.h>

#define TT 300

// ---------------- static scratch (no allocations allowed) ----------------
__device__ float g_a [78643200];   // conv/pool outputs (max: layer1, 16*16*32*32*300)
__device__ float g_sA[78643200];   // spike ping buffer
__device__ float g_sB[19660800];   // spike pong buffer
__device__ float g_u [48000];      // dense pre-psp output

// ---------------- double-float constant splits (compile-time folded) ------
// eps[k] = (k/10)*e*d^k, d = exp(-0.1). Truncation at k<=99 via delayed tail IIR.
constexpr double DDd  = 0.9048374180359595;    // exp(-0.1)
constexpr double CC1d = 0.2718281828459045;    // e/10
constexpr double CC2d = 1.2340980408667956e-3; // 10*exp(-9)
constexpr double CC3d = 1.2340980408667956e-5; // 0.1*exp(-9)
constexpr float DD_H  = (float)DDd;
constexpr float DD_L  = (float)(DDd  - (double)DD_H);
constexpr float CC1_H = (float)CC1d;
constexpr float CC1_L = (float)(CC1d - (double)CC1_H);
constexpr float CC2_H = (float)CC2d;
constexpr float CC2_L = (float)(CC2d - (double)CC2_H);
constexpr float CC3_H = (float)CC3d;

// ---------------- double-float (two-float) primitives ---------------------
struct df { float h, l; };

__device__ __forceinline__ df df_add(df a, df b) {        // TwoSum-based
    float s  = a.h + b.h;
    float bb = s - a.h;
    float e  = (a.h - (s - bb)) + (b.h - bb);
    e += a.l + b.l;
    float h = s + e;
    float l = e - (h - s);
    return {h, l};
}
__device__ __forceinline__ df df_addf(df a, float b) {    // b exact fp32
    float s  = a.h + b;
    float bb = s - a.h;
    float e  = (a.h - (s - bb)) + (b - bb);
    e += a.l;
    float h = s + e;
    float l = e - (h - s);
    return {h, l};
}
__device__ __forceinline__ df df_mulc(df a, float ch, float cl) { // a * df-const
    float p = a.h * ch;
    float e = fmaf(a.h, ch, -p);
    e = fmaf(a.h, cl, e);
    e = fmaf(a.l, ch, e);
    float h = p + e;
    float l = e - (h - p);
    return {h, l};
}

// =====================================================================
// Spatial conv: out[b,co,oh,ow,t] = sum_{ci,kh,kw} W[co,ci,kh,kw]*in[b,ci,ih,iw,t]
// threads = t (coalesced). Per-ci fp32 partial FMA chain (<=25 terms; products
// exact since inputs are binary spikes / exact pool values), partials combined
// via TwoSum-compensated fp32 -> output within ~2e-6 of the true value,
// well inside the reference's own fp32 rounding (~2e-5). No fp64 anywhere.
// =====================================================================
template<int CI,int CO_T,int CO_FULL,int KH,int KW,int HIN,int WIN,int HOUT,int WOUT,int PAD>
__global__ void __launch_bounds__(320)
conv_kernel(const float* __restrict__ in, const float* __restrict__ w,
            float* __restrict__ out, int co_base)
{
    __shared__ __align__(16) float sw[CI*KH*KW*CO_T];
    const int tid = threadIdx.x;
    const int ow = blockIdx.x, oh = blockIdx.y, b = blockIdx.z;

    for (int i = tid; i < CI*KH*KW*CO_T; i += 320) {
        int k = i / CO_T, co = i % CO_T;
        sw[i] = w[(co_base + co)*(CI*KH*KW) + k];
    }
    __syncthreads();

    const int t = tid;
    if (t >= TT) return;

    float acc[CO_T], comp[CO_T];
#pragma unroll
    for (int c = 0; c < CO_T; c++) { acc[c] = 0.f; comp[c] = 0.f; }

    for (int ci = 0; ci < CI; ci++) {
        float pacc[CO_T];
#pragma unroll
        for (int c = 0; c < CO_T; c++) pacc[c] = 0.f;

#pragma unroll
        for (int kh = 0; kh < KH; kh++) {
            const int ih = oh + kh - PAD;
#pragma unroll
            for (int kw = 0; kw < KW; kw++) {
                const int iw = ow + kw - PAD;
                const bool valid = ((unsigned)ih < (unsigned)HIN) && ((unsigned)iw < (unsigned)WIN);
                const float* p = in + ((((b*CI + ci)*HIN + ih)*WIN) + iw)*TT;
                const float x = valid ? p[t] : 0.f;
                const float4* wv = reinterpret_cast<const float4*>(&sw[((ci*KH + kh)*KW + kw)*CO_T]);
#pragma unroll
                for (int c4 = 0; c4 < CO_T/4; c4++) {
                    float4 wq = wv[c4];
                    pacc[c4*4+0] = fmaf(wq.x, x, pacc[c4*4+0]);
                    pacc[c4*4+1] = fmaf(wq.y, x, pacc[c4*4+1]);
                    pacc[c4*4+2] = fmaf(wq.z, x, pacc[c4*4+2]);
                    pacc[c4*4+3] = fmaf(wq.w, x, pacc[c4*4+3]);
                }
            }
        }
        // TwoSum-compensated combine of per-ci partials
#pragma unroll
        for (int c = 0; c < CO_T; c++) {
            float s  = acc[c] + pacc[c];
            float bb = s - acc[c];
            comp[c] += (acc[c] - (s - bb)) + (pacc[c] - bb);
            acc[c]   = s;
        }
    }

#pragma unroll
    for (int c = 0; c < CO_T; c++) {
        float* q = out + ((((b*CO_FULL) + (co_base + c))*HOUT + oh)*WOUT + ow)*TT;
        q[t] = acc[c] + comp[c];
    }
}

// =====================================================================
// SLAYER 2x2 sum-pool, weight 1.1*theta = 11 (exact in fp32 for 0/1 spikes)
// =====================================================================
template<int C,int HIN,int WIN>
__global__ void pool_kernel(const float* __restrict__ in, float* __restrict__ out)
{
    const int HO = HIN/2, WO = WIN/2;
    const int t = blockIdx.x*128 + threadIdx.x;
    if (t >= TT) return;
    const int z  = blockIdx.z;
    const int ho = z % HO;
    const int c  = (z / HO) % C;
    const int b  = z / (HO*C);
    const int wo = blockIdx.y;
    const float* p = in + (((b*C + c)*HIN + 2*ho)*WIN + 2*wo)*TT + t;
    float v = p[0] + p[TT] + p[WIN*TT] + p[(WIN+1)*TT];
    out[(((b*C + c)*HO + ho)*WO + wo)*TT + t] = 11.0f * v;
}

// =====================================================================
// PSP: truncated alpha-kernel conv via double-FLOAT IIR (main pair) +
// plain-fp32 delayed-tail IIR (contribution scaled by ~1e-3, so fp32 error
// lands at ~4e-7 abs). Total error ~1e-6 abs vs true truncated FIR —
// well inside the reference's own ~2e-5 fp32 noise. Fused with the
// bit-exact refractory threshold scan. No fp64 instructions.
// 128 neurons/block; 32-t smem tiles for coalescing.
// =====================================================================
__global__ void __launch_bounds__(128)
psp_spike_kernel(const float* __restrict__ a, float* __restrict__ s, int N)
{
    __shared__ float sa[128][33];
    __shared__ float sd[128][33];
    const int tid  = threadIdx.x;
    const int lane = tid & 31, wid = tid >> 5;
    const int n0 = blockIdx.x * 128;
    const int n  = n0 + tid;

    df Z = {0.f, 0.f}, P = {0.f, 0.f};   // main IIR pair (double-float)
    float P2 = 0.f, Z2 = 0.f;            // tail IIR pair (fp32)
    float r  = 0.f;

    for (int t0 = 0; t0 < TT; t0 += 32) {
        // cooperative coalesced load of current + 100-delayed input tiles
        for (int i = 0; i < 32; i++) {
            const int row = wid*32 + i;
            const int nn  = n0 + row;
            const int t   = t0 + lane;
            float va = 0.f, vd = 0.f;
            if (nn < N) {
                if (t < TT) va = a[nn*TT + t];
                const int td = t - 100;
                if (td >= 0 && td < TT) vd = a[nn*TT + td];
            }
            sa[row][lane] = va;
            sd[row][lane] = vd;
        }
        __syncthreads();

        if (n < N) {
            const int tmax = min(32, TT - t0);
            for (int tt = 0; tt < tmax; tt++) {
                const float x  = sa[tid][tt];
                const float xd = sd[tid][tt];

                // main pair:  Z <- d*(Z + P_old);  P <- d*P_old + x   (df)
                df S  = df_add(Z, P);
                df Zn = df_mulc(S, DD_H, DD_L);
                df Pd = df_mulc(P, DD_H, DD_L);
                P = df_addf(Pd, x);
                Z = Zn;

                // tail pair (fp32 suffices: scaled by CC2/CC3 below)
                Z2 = DD_H * (Z2 + P2);
                P2 = fmaf(DD_H, P2, xd);

                // y = CC1*Z - (CC2*P2 + CC3*Z2)
                df Y = df_mulc(Z, CC1_H, CC1_L);
                float tail = fmaf(CC2_H, P2, fmaf(CC3_H, Z2, CC2_L*P2));
                float y = Y.h + (Y.l - tail);

                const float u  = y + r;
                const float sp = (u >= 10.0f) ? 1.0f : 0.0f;
                r = 0.36787944117144233f * (r - 20.0f * sp);   // exact reference recursion
                sa[tid][tt] = sp;
            }
        }
        __syncthreads();

        // coalesced spike write-out
        for (int i = 0; i < 32; i++) {
            const int row = wid*32 + i;
            const int nn  = n0 + row;
            const int t   = t0 + lane;
            if (nn < N && t < TT) s[nn*TT + t] = sa[row][lane];
        }
        __syncthreads();
    }
}

// =====================================================================
// Dense readout: u[b,o,t] = sum_{chw} s5[b,chw,t] * Wf[o,chw]   (chw = 4096)
// s5 is binary -> products exact; TwoSum-compensated fp32 sum (~1 ulp).
// =====================================================================
__global__ void __launch_bounds__(160)
dense_kernel(const float* __restrict__ s5, const float* __restrict__ wf,
             float* __restrict__ u)
{
    __shared__ float wrow[4096];
    const int b = blockIdx.x, o = blockIdx.y;
    const int tid = threadIdx.x;
    for (int i = tid; i < 4096; i += 160) wrow[i] = wf[o*4096 + i];
    __syncthreads();

    const int t0 = tid, t1 = tid + 160;
    const bool v1 = (t1 < TT);
    float a0 = 0.f, c0 = 0.f, a1 = 0.f, c1 = 0.f;
    const float* p = s5 + (size_t)b * 4096 * TT;
    for (int i = 0; i < 4096; i++) {
        const float wv = wrow[i];
        {   // t0
            const float pr = wv * p[i*TT + t0];        // exact (x in {0,1})
            float sm = a0 + pr;
            float bb = sm - a0;
            c0 += (a0 - (sm - bb)) + (pr - bb);
            a0 = sm;
        }
        if (v1) {   // t1
            const float pr = wv * p[i*TT + t1];
            float sm = a1 + pr;
            float bb = sm - a1;
            c1 += (a1 - (sm - bb)) + (pr - bb);
            a1 = sm;
        }
    }
    float* q = u + (b*10 + o)*TT;
    q[t0] = a0 + c0;
    if (v1) q[t1] = a1 + c1;
}

// =====================================================================
extern "C" void kernel_launch(void* const* d_in, const int* in_sizes, int n_in,
                              void* d_out, int out_size)
{
    const float *s_in = nullptr, *W1 = nullptr, *W2 = nullptr, *W3 = nullptr, *Wf = nullptr;
    for (int i = 0; i < n_in; i++) {
        switch (in_sizes[i]) {
            case 11097600: s_in = (const float*)d_in[i]; break;   // [16,2,34,34,300]
            case 800:      W1   = (const float*)d_in[i]; break;   // [16,2,5,5]
            case 4608:     W2   = (const float*)d_in[i]; break;   // [32,16,3,3]
            case 18432:    W3   = (const float*)d_in[i]; break;   // [64,32,3,3]
            case 40960:    Wf   = (const float*)d_in[i]; break;   // [10,64,8,8]
        }
    }

    float *a, *sA, *sB, *u;
    cudaGetSymbolAddress((void**)&a,  g_a);
    cudaGetSymbolAddress((void**)&sA, g_sA);
    cudaGetSymbolAddress((void**)&sB, g_sB);
    cudaGetSymbolAddress((void**)&u,  g_u);

    // L1: conv 5x5 pad1  [16,2,34,34] -> [16,16,32,32]
    conv_kernel<2,16,16,5,5,34,34,32,32,1><<<dim3(32,32,16),320>>>(s_in, W1, a, 0);
    psp_spike_kernel<<<2048,128>>>(a, sA, 262144);                 // s1

    // pool 2x2 -> [16,16,16,16]
    pool_kernel<16,32,32><<<dim3(3,16,16*16*16),128>>>(sA, a);
    psp_spike_kernel<<<512,128>>>(a, sB, 65536);                   // s2

    // L3: conv 3x3 pad1 [16,16,16,16] -> [16,32,16,16]  (two CO halves)
    conv_kernel<16,16,32,3,3,16,16,16,16,1><<<dim3(16,16,16),320>>>(sB, W2, a, 0);
    conv_kernel<16,16,32,3,3,16,16,16,16,1><<<dim3(16,16,16),320>>>(sB, W2, a, 16);
    psp_spike_kernel<<<1024,128>>>(a, sA, 131072);                 // s3

    // pool -> [16,32,8,8]
    pool_kernel<32,16,16><<<dim3(3,8,16*32*8),128>>>(sA, a);
    psp_spike_kernel<<<256,128>>>(a, sB, 32768);                   // s4

    // L5: conv 3x3 pad1 [16,32,8,8] -> [16,64,8,8]  (four CO quarters)
    conv_kernel<32,16,64,3,3,8,8,8,8,1><<<dim3(8,8,16),320>>>(sB, W3, a, 0);
    conv_kernel<32,16,64,3,3,8,8,8,8,1><<<dim3(8,8,16),320>>>(sB, W3, a, 16);
    conv_kernel<32,16,64,3,3,8,8,8,8,1><<<dim3(8,8,16),320>>>(sB, W3, a, 32);
    conv_kernel<32,16,64,3,3,8,8,8,8,1><<<dim3(8,8,16),320>>>(sB, W3, a, 48);
    psp_spike_kernel<<<512,128>>>(a, sA, 65536);                   // s5

    // dense readout + final psp/spike straight into d_out
    dense_kernel<<<dim3(16,10),160>>>(sA, Wf, u);
    psp_spike_kernel<<<2,128>>>(u, (float*)d_out, 160);
}

// round 9
// speedup vs baseline: 5.9360x; 1.8231x over previous
#include <cuda_runtime.h>

#define TT 300

// ---------------- static scratch (no allocations allowed) ----------------
__device__ float g_a [78643200];   // conv/pool outputs (max: layer1, 16*16*32*32*300)
__device__ float g_sA[78643200];   // spike ping buffer
__device__ float g_sB[19660800];   // spike pong buffer
__device__ float g_u [48000];      // dense pre-psp output (combined)
__device__ float g_up[192000];     // dense split-K partials (4 x 48000)

// ---------------- double-float constant splits (compile-time folded) ------
// eps[k] = (k/10)*e*d^k, d = exp(-0.1). Truncation at k<=99 via delayed tail IIR.
constexpr double DDd   = 0.9048374180359595;     // exp(-0.1)
constexpr double D2d   = 0.8187307530779818;     // exp(-0.2)
constexpr double TD2d  = 1.6374615061559637;     // 2*exp(-0.2)
constexpr double CC1d  = 0.2718281828459045;     // e/10
constexpr double CC2d  = 1.2340980408667956e-3;  // 10*exp(-9)
constexpr double CC3d  = 1.2340980408667956e-5;  // 0.1*exp(-9)
constexpr float DD_H   = (float)DDd;
constexpr float DD_L   = (float)(DDd   - (double)DD_H);
constexpr float D2_H   = (float)D2d;
constexpr float D2_L   = (float)(D2d   - (double)D2_H);
constexpr float TD2_H  = (float)TD2d;
constexpr float TD2_L  = (float)(TD2d  - (double)TD2_H);
constexpr float CC1_H  = (float)CC1d;
constexpr float CC1_L  = (float)(CC1d  - (double)CC1_H);
constexpr float CC2_H  = (float)CC2d;
constexpr float CC2_L  = (float)(CC2d  - (double)CC2_H);
constexpr float CC3_H  = (float)CC3d;

// ---------------- double-float (two-float) primitives ---------------------
struct df { float h, l; };

__device__ __forceinline__ df df_add(df a, df b) {        // TwoSum-based
    float s  = a.h + b.h;
    float bb = s - a.h;
    float e  = (a.h - (s - bb)) + (b.h - bb);
    e += a.l + b.l;
    float h = s + e;
    float l = e - (h - s);
    return {h, l};
}
__device__ __forceinline__ df df_addf(df a, float b) {    // b exact fp32
    float s  = a.h + b;
    float bb = s - a.h;
    float e  = (a.h - (s - bb)) + (b - bb);
    e += a.l;
    float h = s + e;
    float l = e - (h - s);
    return {h, l};
}
__device__ __forceinline__ df df_mulc(df a, float ch, float cl) { // a * df-const
    float p = a.h * ch;
    float e = fmaf(a.h, ch, -p);
    e = fmaf(a.h, cl, e);
    e = fmaf(a.l, ch, e);
    float h = p + e;
    float l = e - (h - p);
    return {h, l};
}

// =====================================================================
// Spatial conv: out[b,co,oh,ow,t] = sum_{ci,kh,kw} W[co,ci,kh,kw]*in[b,ci,ih,iw,t]
// threads = t (coalesced). Per-ci fp32 partial FMA chain, partials combined
// via TwoSum-compensated fp32 -> ~2e-6 of true value. CO splits folded into
// blockIdx.z (z = b + 16*co_group) so each layer is ONE launch.
// =====================================================================
template<int CI,int CO_T,int CO_FULL,int KH,int KW,int HIN,int WIN,int HOUT,int WOUT,int PAD>
__global__ void __launch_bounds__(320)
conv_kernel(const float* __restrict__ in, const float* __restrict__ w,
            float* __restrict__ out)
{
    __shared__ __align__(16) float sw[CI*KH*KW*CO_T];
    const int tid = threadIdx.x;
    const int ow = blockIdx.x, oh = blockIdx.y;
    const int b = blockIdx.z & 15;
    const int co_base = (blockIdx.z >> 4) * CO_T;

    for (int i = tid; i < CI*KH*KW*CO_T; i += 320) {
        int k = i / CO_T, co = i % CO_T;
        sw[i] = w[(co_base + co)*(CI*KH*KW) + k];
    }
    __syncthreads();

    const int t = tid;
    if (t >= TT) return;

    float acc[CO_T], comp[CO_T];
#pragma unroll
    for (int c = 0; c < CO_T; c++) { acc[c] = 0.f; comp[c] = 0.f; }

    for (int ci = 0; ci < CI; ci++) {
        float pacc[CO_T];
#pragma unroll
        for (int c = 0; c < CO_T; c++) pacc[c] = 0.f;

#pragma unroll
        for (int kh = 0; kh < KH; kh++) {
            const int ih = oh + kh - PAD;
#pragma unroll
            for (int kw = 0; kw < KW; kw++) {
                const int iw = ow + kw - PAD;
                const bool valid = ((unsigned)ih < (unsigned)HIN) && ((unsigned)iw < (unsigned)WIN);
                const float* p = in + ((((b*CI + ci)*HIN + ih)*WIN) + iw)*TT;
                const float x = valid ? p[t] : 0.f;
                const float4* wv = reinterpret_cast<const float4*>(&sw[((ci*KH + kh)*KW + kw)*CO_T]);
#pragma unroll
                for (int c4 = 0; c4 < CO_T/4; c4++) {
                    float4 wq = wv[c4];
                    pacc[c4*4+0] = fmaf(wq.x, x, pacc[c4*4+0]);
                    pacc[c4*4+1] = fmaf(wq.y, x, pacc[c4*4+1]);
                    pacc[c4*4+2] = fmaf(wq.z, x, pacc[c4*4+2]);
                    pacc[c4*4+3] = fmaf(wq.w, x, pacc[c4*4+3]);
                }
            }
        }
        // TwoSum-compensated combine of per-ci partials
#pragma unroll
        for (int c = 0; c < CO_T; c++) {
            float s  = acc[c] + pacc[c];
            float bb = s - acc[c];
            comp[c] += (acc[c] - (s - bb)) + (pacc[c] - bb);
            acc[c]   = s;
        }
    }

#pragma unroll
    for (int c = 0; c < CO_T; c++) {
        float* q = out + ((((b*CO_FULL) + (co_base + c))*HOUT + oh)*WOUT + ow)*TT;
        q[t] = acc[c] + comp[c];
    }
}

// =====================================================================
// SLAYER 2x2 sum-pool, weight 1.1*theta = 11 (exact in fp32 for 0/1 spikes)
// =====================================================================
template<int C,int HIN,int WIN>
__global__ void pool_kernel(const float* __restrict__ in, float* __restrict__ out)
{
    const int HO = HIN/2, WO = WIN/2;
    const int t = blockIdx.x*128 + threadIdx.x;
    if (t >= TT) return;
    const int z  = blockIdx.z;
    const int ho = z % HO;
    const int c  = (z / HO) % C;
    const int b  = z / (HO*C);
    const int wo = blockIdx.y;
    const float* p = in + (((b*C + c)*HIN + 2*ho)*WIN + 2*wo)*TT + t;
    float v = p[0] + p[TT] + p[WIN*TT] + p[(WIN+1)*TT];
    out[(((b*C + c)*HO + ho)*WO + wo)*TT + t] = 11.0f * v;
}

// =====================================================================
// PSP: truncated alpha-kernel conv via double-float IIR (2-STEP BLOCKED:
// Z_{t+2} = d^2 Z + 2d^2 P + d(x)x_t, P_{t+2} = d^2 P + d(x)x_t + x_{t+1},
// products exact via TwoProd -> state accuracy ~1e-9, critical path halved)
// + plain-fp32 delayed-tail IIR, fused with the bit-exact refractory scan.
// float4 cooperative loads/stores; next tile register-prefetched during
// the serial IIR compute. 128 neurons/block; 32-t tiles.
// =====================================================================
__global__ void __launch_bounds__(128)
psp_spike_kernel(const float* __restrict__ a, float* __restrict__ s, int N)
{
    __shared__ __align__(16) float sx[128][36];   // current tile (spikes in-place)
    __shared__ __align__(16) float sd[128][36];   // 100-delayed tile
    const int tid = threadIdx.x;
    const int n0 = blockIdx.x * 128;
    const int n  = n0 + tid;

    df Z = {0.f, 0.f}, P = {0.f, 0.f};   // main IIR pair (double-float)
    float Z2t = 0.f, P2t = 0.f;          // tail IIR pair (fp32)
    float r   = 0.f;

    float4 curv[8], delv[8];

    // ---- prefetch tile 0 ----
#pragma unroll
    for (int q = 0; q < 8; q++) {
        const int flat = q*128 + tid;
        const int row = flat >> 3, c4 = flat & 7;
        const int nn = n0 + row;
        const int t = 0 + c4*4;
        float4 v = {0.f,0.f,0.f,0.f}, wv = {0.f,0.f,0.f,0.f};
        if (nn < N && t < TT)
            v = *reinterpret_cast<const float4*>(a + (size_t)nn*TT + t);
        curv[q] = v; delv[q] = wv;   // delayed all-invalid at tile 0
    }

    for (int t0 = 0; t0 < TT; t0 += 32) {
        // ---- stage prefetched tile into smem ----
#pragma unroll
        for (int q = 0; q < 8; q++) {
            const int flat = q*128 + tid;
            const int row = flat >> 3, c4 = flat & 7;
            *reinterpret_cast<float4*>(&sx[row][c4*4]) = curv[q];
            *reinterpret_cast<float4*>(&sd[row][c4*4]) = delv[q];
        }
        __syncthreads();

        // ---- prefetch NEXT tile (overlaps the serial IIR below) ----
        const int t0n = t0 + 32;
        if (t0n < TT) {
#pragma unroll
            for (int q = 0; q < 8; q++) {
                const int flat = q*128 + tid;
                const int row = flat >> 3, c4 = flat & 7;
                const int nn = n0 + row;
                const int t = t0n + c4*4;
                float4 v = {0.f,0.f,0.f,0.f}, wv = {0.f,0.f,0.f,0.f};
                if (nn < N) {
                    if (t < TT)
                        v = *reinterpret_cast<const float4*>(a + (size_t)nn*TT + t);
                    const int td = t - 100;
                    if (td >= 0 && td < TT)
                        wv = *reinterpret_cast<const float4*>(a + (size_t)nn*TT + td);
                }
                curv[q] = v; delv[q] = wv;
            }
        }

        // ---- 2-step-blocked df IIR + refractory scan ----
        if (n < N) {
            const int tmax = min(32, TT - t0);    // 32 or 12, both /4
            for (int tq = 0; tq < tmax; tq += 4) {
                float4 X  = *reinterpret_cast<const float4*>(&sx[tid][tq]);
                float4 XD = *reinterpret_cast<const float4*>(&sd[tid][tq]);
                float sp[4];
#pragma unroll
                for (int h = 0; h < 2; h++) {
                    const float x0  = (h == 0) ? X.x  : X.z;
                    const float x1  = (h == 0) ? X.y  : X.w;
                    const float xd0 = (h == 0) ? XD.x : XD.z;
                    const float xd1 = (h == 0) ? XD.y : XD.w;

                    // Z1 = d*(Z+P)  (for y0)
                    df S  = df_add(Z, P);
                    df Z1 = df_mulc(S, DD_H, DD_L);
                    // dx0 = d (x) x0, exact product
                    float ph = DD_H * x0;
                    float pl = fmaf(DD_H, x0, -ph);
                    pl = fmaf(DD_L, x0, pl);
                    // Z_{t+2} = d^2 Z + 2 d^2 P + dx0
                    df A = df_mulc(Z, D2_H, D2_L);
                    df B = df_mulc(P, TD2_H, TD2_L);
                    df Znew = df_add(df_add(A, B), df{ph, pl});
                    // P_{t+2} = d^2 P + dx0 + x1
                    df Cv = df_mulc(P, D2_H, D2_L);
                    df Pnew = df_addf(df_add(Cv, df{ph, pl}), x1);

                    // tail step 0 (fp32) + y0 + spike
                    Z2t = DD_H * (Z2t + P2t);
                    P2t = fmaf(DD_H, P2t, xd0);
                    float tail0 = fmaf(CC2_H, P2t, fmaf(CC3_H, Z2t, CC2_L * P2t));
                    df Y0 = df_mulc(Z1, CC1_H, CC1_L);
                    float y0 = Y0.h + (Y0.l - tail0);
                    float u0 = y0 + r;
                    float s0 = (u0 >= 10.0f) ? 1.0f : 0.0f;
                    r = 0.36787944117144233f * (r - 20.0f * s0);

                    // tail step 1 + y1 + spike
                    Z2t = DD_H * (Z2t + P2t);
                    P2t = fmaf(DD_H, P2t, xd1);
                    float tail1 = fmaf(CC2_H, P2t, fmaf(CC3_H, Z2t, CC2_L * P2t));
                    df Y1 = df_mulc(Znew, CC1_H, CC1_L);
                    float y1 = Y1.h + (Y1.l - tail1);
                    float u1 = y1 + r;
                    float s1 = (u1 >= 10.0f) ? 1.0f : 0.0f;
                    r = 0.36787944117144233f * (r - 20.0f * s1);

                    Z = Znew; P = Pnew;
                    sp[h*2+0] = s0; sp[h*2+1] = s1;
                }
                // spikes back in place (thread owns its row)
                float4 SP = {sp[0], sp[1], sp[2], sp[3]};
                *reinterpret_cast<float4*>(&sx[tid][tq]) = SP;
            }
        }
        __syncthreads();

        // ---- cooperative float4 spike write-out ----
#pragma unroll
        for (int q = 0; q < 8; q++) {
            const int flat = q*128 + tid;
            const int row = flat >> 3, c4 = flat & 7;
            const int nn = n0 + row;
            const int t = t0 + c4*4;
            if (nn < N && t < TT)
                *reinterpret_cast<float4*>(s + (size_t)nn*TT + t) =
                    *reinterpret_cast<const float4*>(&sx[row][c4*4]);
        }
        __syncthreads();   // sx reused next tile
    }
}

// =====================================================================
// Dense readout, split-K x4: up[z][b][o][t] = sum_{i in chunk z} s5 * Wf
// s5 binary -> products exact; TwoSum-compensated fp32 chunk sums.
// =====================================================================
__global__ void __launch_bounds__(320)
dense_partial_kernel(const float* __restrict__ s5, const float* __restrict__ wf,
                     float* __restrict__ up)
{
    __shared__ float wrow[1024];
    const int b = blockIdx.x, o = blockIdx.y, z = blockIdx.z;
    const int tid = threadIdx.x;
    for (int i = tid; i < 1024; i += 320) wrow[i] = wf[o*4096 + z*1024 + i];
    __syncthreads();
    if (tid >= TT) return;

    const float* p = s5 + (size_t)b * 4096 * TT + (size_t)z * 1024 * TT;
    float acc = 0.f, comp = 0.f;
    for (int i = 0; i < 1024; i++) {
        const float pr = wrow[i] * p[i*TT + tid];   // exact (x in {0,1})
        float sm = acc + pr;
        float bb = sm - acc;
        comp += (acc - (sm - bb)) + (pr - bb);
        acc = sm;
    }
    up[(size_t)z*48000 + (b*10 + o)*TT + tid] = acc + comp;
}

__global__ void dense_combine_kernel(const float* __restrict__ up, float* __restrict__ u)
{
    const int i = blockIdx.x*256 + threadIdx.x;
    if (i >= 48000) return;
    u[i] = ((up[i] + up[48000 + i]) + up[96000 + i]) + up[144000 + i];
}

// =====================================================================
extern "C" void kernel_launch(void* const* d_in, const int* in_sizes, int n_in,
                              void* d_out, int out_size)
{
    const float *s_in = nullptr, *W1 = nullptr, *W2 = nullptr, *W3 = nullptr, *Wf = nullptr;
    for (int i = 0; i < n_in; i++) {
        switch (in_sizes[i]) {
            case 11097600: s_in = (const float*)d_in[i]; break;   // [16,2,34,34,300]
            case 800:      W1   = (const float*)d_in[i]; break;   // [16,2,5,5]
            case 4608:     W2   = (const float*)d_in[i]; break;   // [32,16,3,3]
            case 18432:    W3   = (const float*)d_in[i]; break;   // [64,32,3,3]
            case 40960:    Wf   = (const float*)d_in[i]; break;   // [10,64,8,8]
        }
    }

    float *a, *sA, *sB, *u, *up;
    cudaGetSymbolAddress((void**)&a,  g_a);
    cudaGetSymbolAddress((void**)&sA, g_sA);
    cudaGetSymbolAddress((void**)&sB, g_sB);
    cudaGetSymbolAddress((void**)&u,  g_u);
    cudaGetSymbolAddress((void**)&up, g_up);

    // L1: conv 5x5 pad1  [16,2,34,34] -> [16,16,32,32]
    conv_kernel<2,16,16,5,5,34,34,32,32,1><<<dim3(32,32,16),320>>>(s_in, W1, a);
    psp_spike_kernel<<<2048,128>>>(a, sA, 262144);                 // s1

    // pool 2x2 -> [16,16,16,16]
    pool_kernel<16,32,32><<<dim3(3,16,16*16*16),128>>>(sA, a);
    psp_spike_kernel<<<512,128>>>(a, sB, 65536);                   // s2

    // L3: conv 3x3 pad1 [16,16,16,16] -> [16,32,16,16]  (one launch, z = b + 16*half)
    conv_kernel<16,16,32,3,3,16,16,16,16,1><<<dim3(16,16,32),320>>>(sB, W2, a);
    psp_spike_kernel<<<1024,128>>>(a, sA, 131072);                 // s3

    // pool -> [16,32,8,8]
    pool_kernel<32,16,16><<<dim3(3,8,16*32*8),128>>>(sA, a);
    psp_spike_kernel<<<256,128>>>(a, sB, 32768);                   // s4

    // L5: conv 3x3 pad1 [16,32,8,8] -> [16,64,8,8]  (one launch, z = b + 16*quarter)
    conv_kernel<32,16,64,3,3,8,8,8,8,1><<<dim3(8,8,64),320>>>(sB, W3, a);
    psp_spike_kernel<<<512,128>>>(a, sA, 65536);                   // s5

    // dense readout (split-K x4) + combine + final psp/spike into d_out
    dense_partial_kernel<<<dim3(16,10,4),320>>>(sA, Wf, up);
    dense_combine_kernel<<<188,256>>>(up, u);
    psp_spike_kernel<<<2,128>>>(u, (float*)d_out, 160);
}